// round 12
// baseline (speedup 1.0000x reference)
#include <cuda_runtime.h>
#include <math.h>
#include <stdint.h>

// ---------------- problem constants ----------------
#define Nn 4096
#define Dd 64
#define HKk 256
#define BM 128
#define BN 128
#define NRB 32
#define NCB 4
#define CHUNK 1024
#define TPC 8
#define OUTPLANE 262144
#define L2E10 14.426950408889634f
#define LN2 0.6931471805599453f

typedef unsigned long long ull;

// ---------------- static device scratch ----------------
__device__ float g_zf[Nn*Dd];
__device__ float g_zf_hi[Nn*Dd], g_zf_lo[Nn*Dd];   // scaled by 2 (A side)
__device__ float g_zsP[Nn*128];                    // B side: [row][hi 64 perm | lo 64 perm]
__device__ float g_zf2[Nn], g_zs2[Nn], g_phi1[Nn], g_phi2[Nn];
__device__ float g_w1m[Dd], g_w2m[Dd], g_b1m, g_b2m;
__device__ unsigned g_aph1, g_aph2;
// transposed partials: rows [i][cb], cols [col][rb]
__device__ float g_r_m[Nn*NCB], g_r_s[Nn*NCB], g_r_bc[Nn*NCB];
__device__ int   g_r_bj[Nn*NCB];
__device__ float g_c_m[Nn*NRB], g_c_s[Nn*NRB];
__device__ int   g_idx[Nn];
__device__ float g_lse1[Nn], g_lse2[Nn];

// ---------------- f32x2 packed helpers ----------------
#define FMA2(d,a,b,c) asm("fma.rn.f32x2 %0, %1, %2, %3;" : "=l"(d) : "l"(a), "l"(b), "l"(c))
#define ADD2(d,a,b)   asm("add.rn.f32x2 %0, %1, %2;"     : "=l"(d) : "l"(a), "l"(b))
#define MUL2(d,a,b)   asm("mul.rn.f32x2 %0, %1, %2;"     : "=l"(d) : "l"(a), "l"(b))

__device__ __forceinline__ ull dup2(float x) {
    ull r; asm("mov.b64 %0, {%1, %1};" : "=l"(r) : "f"(x)); return r;
}
__device__ __forceinline__ ull pk2(float lo, float hi) {
    ull r; asm("mov.b64 %0, {%1, %2};" : "=l"(r) : "f"(lo), "f"(hi)); return r;
}
__device__ __forceinline__ float2 asf2(ull v) {
    float2 f; asm("mov.b64 {%0, %1}, %2;" : "=f"(f.x), "=f"(f.y) : "l"(v)); return f;
}

struct PC { ull MAG, NMAG, NEG1, D3, D2, D1, ONE, L2; };
__device__ __forceinline__ PC make_pc() {
    PC K;
    K.MAG  = dup2(12582912.0f);
    K.NMAG = dup2(-12582912.0f);
    K.NEG1 = dup2(-1.0f);
    K.D3   = dup2(0.0558367f);
    K.D2   = dup2(0.2414282f);
    K.D1   = dup2(0.6931472f);
    K.ONE  = dup2(1.0f);
    K.L2   = dup2(L2E10);
    return K;
}

// acc += exp2(t) (deg-3; args <= 0; underflow clamps to 0)
__device__ __forceinline__ void pexp2acc(ull &acc, ull t, const PC& K) {
    ull tb; ADD2(tb, t, K.MAG);
    ull rr; ADD2(rr, tb, K.NMAG);
    ull f;  FMA2(f, rr, K.NEG1, t);
    ull p = K.D3;
    FMA2(p, p, f, K.D2);
    FMA2(p, p, f, K.D1);
    FMA2(p, p, f, K.ONE);
    int elo = (int)(unsigned)tb         + (127 - 0x4B400000);
    int ehi = (int)(unsigned)(tb >> 32) + (127 - 0x4B400000);
    elo = elo < 0 ? 0 : elo;
    ehi = ehi < 0 ? 0 : ehi;
    ull sc = pk2(__int_as_float(elo << 23), __int_as_float(ehi << 23));
    FMA2(acc, p, sc, acc);
}

// scalar exp2 (deg-5, merges only)
__device__ __forceinline__ float fexp2(float x) {
    float t  = fmaxf(x, -126.0f);
    float tb = t + 12582912.0f;
    int   ni = __float_as_int(tb);
    float r  = tb - 12582912.0f;
    float f  = t - r;
    float p  = 0.00133335581f;
    p = fmaf(p, f, 0.00961812910f);
    p = fmaf(p, f, 0.0555041087f);
    p = fmaf(p, f, 0.240226507f);
    p = fmaf(p, f, 0.693147180f);
    p = fmaf(p, f, 1.0f);
    float sc = __int_as_float((ni + (127 - 0x4B400000)) << 23);
    return p * sc;
}

__device__ __forceinline__ unsigned fenc(float f) {
    unsigned u = __float_as_uint(f);
    return (u & 0x80000000u) ? ~u : (u | 0x80000000u);
}
__device__ __forceinline__ float fdec(unsigned u) {
    return (u & 0x80000000u) ? __uint_as_float(u & 0x7fffffffu) : __uint_as_float(~u);
}

__device__ __forceinline__ float tf32_hi(float x) {
    uint32_t h; asm("cvt.rna.tf32.f32 %0, %1;" : "=r"(h) : "f"(x));
    return __uint_as_float(h);
}

// mma.sync m16n8k8 tf32
__device__ __forceinline__ void mma8(float* d, const uint4& a, const uint2& b) {
    asm("mma.sync.aligned.m16n8k8.row.col.f32.tf32.tf32.f32 "
        "{%0,%1,%2,%3}, {%4,%5,%6,%7}, {%8,%9}, {%0,%1,%2,%3};"
        : "+f"(d[0]), "+f"(d[1]), "+f"(d[2]), "+f"(d[3])
        : "r"(a.x), "r"(a.y), "r"(a.z), "r"(a.w), "r"(b.x), "r"(b.y));
}

// ---------------- cp.async ----------------
#define CPASYNC16(s, g) asm volatile("cp.async.cg.shared.global [%0], [%1], 16;" :: "r"(s), "l"(g))
#define CPASYNC4(s, g)  asm volatile("cp.async.ca.shared.global [%0], [%1], 4;"  :: "r"(s), "l"(g))
#define CP_COMMIT       asm volatile("cp.async.commit_group;" ::: "memory")
#define CP_WAIT(n)      asm volatile("cp.async.wait_group %0;" :: "n"(n) : "memory")

__device__ __forceinline__ uint32_t smem_u32(const void* p) {
    uint32_t a;
    asm("{ .reg .u64 t; cvta.to.shared.u64 t, %1; cvt.u32.u64 %0, t; }" : "=r"(a) : "l"(p));
    return a;
}

// ---------------- smem layout (bytes) ----------------
#define BROW 544
#define BBUF (128*BROW)
#define OFF_A    0
#define OFF_ALO  32768
#define OFF_B    65536
#define OFF_ZS2(b) (204800 + (b)*512)
#define OFF_P1(b)  (205824 + (b)*512)
#define OFF_NZF2 206848
#define OFF_P2   207360
#define OFF_COLM 207872
#define OFF_COLS 211968
#define OFF_ROWM 216064
#define OFF_ROWS 218112
#define OFF_ROWB 220160
#define OFF_ROWJ 222208
#define SMEM_BYTES (224256 + 1024)

// ---------------- k0tr ----------------
__global__ void k0tr(const float* __restrict__ z,
                     const float* __restrict__ w1, const float* __restrict__ b1,
                     const float* __restrict__ w2, const float* __restrict__ b2) {
    __shared__ float tsh[32][33];
    int tid = threadIdx.x;
    int blk = blockIdx.x;
    if (blk == 256) {
        int d = tid >> 2, part = tid & 3;
        float s1 = 0.f, s2 = 0.f;
        for (int k = part*64; k < part*64 + 64; ++k) {
            s1 += w1[d*HKk + k]; s2 += w2[d*HKk + k];
        }
        s1 += __shfl_xor_sync(0xffffffffu, s1, 1);
        s1 += __shfl_xor_sync(0xffffffffu, s1, 2);
        s2 += __shfl_xor_sync(0xffffffffu, s2, 1);
        s2 += __shfl_xor_sync(0xffffffffu, s2, 2);
        if (part == 0) { g_w1m[d] = s1 / (float)HKk; g_w2m[d] = s2 / (float)HKk; }
        if (tid < 64) {
            const float* bb = (tid < 32) ? b1 : b2;
            int l = tid & 31;
            float s = 0.f;
            for (int k = l; k < HKk; k += 32) s += bb[k];
            #pragma unroll
            for (int o = 16; o > 0; o >>= 1) s += __shfl_xor_sync(0xffffffffu, s, o);
            if (l == 0) {
                if (tid < 32) { g_b1m = s / (float)HKk; g_aph1 = 0u; }
                else          { g_b2m = s / (float)HKk; g_aph2 = 0u; }
            }
        }
        return;
    }
    int bx = blk & 7, by = blk >> 3;
    int tx = tid & 31, ty = tid >> 5;
    int x = bx*32 + tx;
    #pragma unroll
    for (int q = 0; q < 4; ++q) {
        int row = by*32 + ty + q*8;
        tsh[ty + q*8][tx] = z[row*256 + x];
    }
    __syncthreads();
    #pragma unroll
    for (int q = 0; q < 4; ++q) {
        int col = bx*32 + ty + q*8;
        int row = by*32 + tx;
        g_zf[col*1024 + row] = tsh[tx][ty + q*8];
    }
}

// ---------------- k1 ----------------
__global__ void k1(const float* __restrict__ codebook, const float* __restrict__ noise) {
    int warp = threadIdx.x >> 5, lane = threadIdx.x & 31;
    int row = blockIdx.x*4 + warp;
    const float* crow = codebook + (row >> 3) * (2*Dd);
    const float* nrow = noise + row*Dd;
    const float* frow = g_zf + row*Dd;
    float zs2 = 0.f, p1 = 0.f, zf2 = 0.f, p2 = 0.f;
    #pragma unroll
    for (int q = 0; q < 2; ++q) {
        int d = lane + q*32;
        float mu  = crow[d];
        float cov = expf(crow[Dd + d]);
        float zs  = mu + cov * nrow[d];
        float zh = tf32_hi(zs);
        int pos = ((d >> 3) << 3) + ((d & 3) << 1) + ((d >> 2) & 1);
        g_zsP[row*128 + pos]      = zh;
        g_zsP[row*128 + 64 + pos] = tf32_hi(zs - zh);
        zs2 += zs*zs;
        p1  += zs * g_w1m[d];
        float zf = frow[d];
        float fh = tf32_hi(zf);
        g_zf_hi[row*Dd + d] = 2.0f * fh;
        g_zf_lo[row*Dd + d] = 2.0f * tf32_hi(zf - fh);
        zf2 += zf*zf;
        p2  += zf * g_w2m[d];
    }
    #pragma unroll
    for (int o = 16; o > 0; o >>= 1) {
        zs2 += __shfl_xor_sync(0xffffffffu, zs2, o);
        p1  += __shfl_xor_sync(0xffffffffu, p1,  o);
        zf2 += __shfl_xor_sync(0xffffffffu, zf2, o);
        p2  += __shfl_xor_sync(0xffffffffu, p2,  o);
    }
    if (lane == 0) {
        float phi1 = p1 + g_b1m, phi2 = p2 + g_b2m;
        g_zs2[row] = zs2;  g_phi1[row] = phi1;
        g_zf2[row] = zf2;  g_phi2[row] = phi2;
        atomicMax(&g_aph1, fenc(phi1));
        atomicMax(&g_aph2, fenc(phi2));
    }
}

// ---------------- k2: phase-split warp scheduling ----------------
__global__ void __launch_bounds__(512, 1) k2() {
    extern __shared__ char smem_raw[];
    char* sb = (char*)(((uintptr_t)smem_raw + 1023) & ~(uintptr_t)1023);
    const uint32_t sba = smem_u32(sb);

    const int tid  = threadIdx.x;
    const int lane = tid & 31, wid = tid >> 5;
    const int rw = wid >> 2, cw = wid & 3;
    const int q  = lane & 3,  g  = lane >> 2;
    const int ph0 = wid & 1;                  // phase order alternation
    const int rb = blockIdx.x, cb = blockIdx.y;
    const int i0 = rb * BM;
    const float S1g = L2E10 * fdec(g_aph1);
    const float S2g = L2E10 * fdec(g_aph2);
    const PC K = make_pc();

    float* nzf2s = (float*)(sb + OFF_NZF2);
    float* p2s   = (float*)(sb + OFF_P2);
    float* colm  = (float*)(sb + OFF_COLM);
    float* colsm = (float*)(sb + OFF_COLS);
    float* rowm  = (float*)(sb + OFF_ROWM);
    float* rowss = (float*)(sb + OFF_ROWS);
    float* rowb  = (float*)(sb + OFF_ROWB);
    int*   rowj  = (int*)  (sb + OFF_ROWJ);

    // ---- prologue: prefetch tile 0 (buf 0) ----
    {
        const int j0 = cb*CHUNK;
        for (int idx = tid; idx < 4096; idx += 512) {
            int row = idx >> 5, ch = idx & 31;
            CPASYNC16(sba + OFF_B + row*BROW + ch*16, g_zsP + (j0 + row)*128 + ch*4);
        }
        if (tid < 128) {
            CPASYNC4(sba + OFF_ZS2(0) + tid*4, g_zs2 + j0 + tid);
            CPASYNC4(sba + OFF_P1(0)  + tid*4, g_phi1 + j0 + tid);
        }
        CP_COMMIT;
    }

    // ---- stage A fragments + row scalars ----
    {
        float4* Ah = (float4*)(sb + OFF_A);
        float4* Al = (float4*)(sb + OFF_ALO);
        for (int t2 = tid; t2 < 2048; t2 += 512) {
            int kt = t2 >> 8, mt = (t2 >> 5) & 7, l = t2 & 31;
            int r0 = (i0 + mt*16 + (l >> 2)) * 64;
            int r8 = r0 + 8*64;
            int c0 = kt*8 + (l & 3);
            float4 v;
            v.x = g_zf_hi[r0 + c0];
            v.y = g_zf_hi[r8 + c0];
            v.z = g_zf_hi[r0 + c0 + 4];
            v.w = g_zf_hi[r8 + c0 + 4];
            Ah[t2] = v;
            v.x = g_zf_lo[r0 + c0];
            v.y = g_zf_lo[r8 + c0];
            v.z = g_zf_lo[r0 + c0 + 4];
            v.w = g_zf_lo[r8 + c0 + 4];
            Al[t2] = v;
        }
        if (tid < 128) {
            nzf2s[tid] = -g_zf2[i0 + tid];
            p2s[tid]   = g_phi2[i0 + tid];
        }
    }
    __syncthreads();

    float nzf2row[4], p2row[4];
    #pragma unroll
    for (int m = 0; m < 2; ++m)
        #pragma unroll
        for (int h = 0; h < 2; ++h) {
            int row = (rw*2 + m)*16 + h*8 + g;
            nzf2row[m*2+h] = nzf2s[row];
            p2row[m*2+h]   = p2s[row];
        }

    float bq[4], shift[4]; int bj[4]; ull rs2[4];
    #pragma unroll
    for (int s = 0; s < 4; ++s) { bq[s] = -3e38f; shift[s] = -1e30f; bj[s] = 0x7fffffff; rs2[s] = 0ull; }

    const uint4* Ah = (const uint4*)(sb + OFF_A);
    const uint4* Al = (const uint4*)(sb + OFF_ALO);
    const int browoff = (cw*32 + g)*BROW;

    for (int t = 0; t < TPC; ++t) {
        const int buf = t & 1;
        const int j0 = cb*CHUNK + t*BN;

        CP_WAIT(0);            // this thread's pending group (tile t data) arrived
        __syncthreads();       // all warps: done with body t-1, tile-t data globally visible

        // ---- merge previous tile's col partials (16 threads, overlaps others' GEMM) ----
        if (t > 0 && rw == 0 && g == 0) {
            const int pv = (t - 1) & 1;
            const int pj0 = cb*CHUNK + (t - 1)*BN;
            const float* cmm = colm + pv*512;
            const float* css = colsm + pv*512;
            #pragma unroll
            for (int s = 0; s < 8; ++s) {
                int col = cw*32 + (s >> 1)*8 + 2*q + (s & 1);
                float m0 = cmm[col], m1 = cmm[128 + col], m2 = cmm[256 + col], m3 = cmm[384 + col];
                float M = fmaxf(fmaxf(m0, m1), fmaxf(m2, m3));
                float S = css[col]*fexp2(m0 - M) + css[128 + col]*fexp2(m1 - M)
                        + css[256 + col]*fexp2(m2 - M) + css[384 + col]*fexp2(m3 - M);
                g_c_m[(pj0 + col)*NRB + rb] = M;
                g_c_s[(pj0 + col)*NRB + rb] = S;
            }
        }

        // ---- prefetch tile t+1 (safe: barrier above covers buf reuse) ----
        if (t + 1 < TPC) {
            const int nb = (t + 1) & 1;
            const int nj0 = cb*CHUNK + (t + 1)*BN;
            for (int idx = tid; idx < 4096; idx += 512) {
                int row = idx >> 5, ch = idx & 31;
                CPASYNC16(sba + OFF_B + nb*BBUF + row*BROW + ch*16, g_zsP + (nj0 + row)*128 + ch*4);
            }
            if (tid < 128) {
                CPASYNC4(sba + OFF_ZS2(nb) + tid*4, g_zs2 + nj0 + tid);
                CPASYNC4(sba + OFF_P1(nb)  + tid*4, g_phi1 + nj0 + tid);
            }
            CP_COMMIT;
        }

        const char* bb = sb + OFF_B + buf*BBUF + browoff;
        const float* zs2raw = (const float*)(sb + OFF_ZS2(buf));
        const float* p1raw  = (const float*)(sb + OFF_P1(buf));

        // ---- two phases over n-frag pairs; odd warps reverse order ----
        #pragma unroll
        for (int phase = 0; phase < 2; ++phase) {
            const int pair = ph0 ^ phase;     // 0 -> frags {0,1}, 1 -> frags {2,3}

            // GEMM for this pair: d[m][nn][e]
            float d[2][2][4];
            #pragma unroll
            for (int m = 0; m < 2; ++m)
                #pragma unroll
                for (int nn = 0; nn < 2; ++nn)
                    #pragma unroll
                    for (int e = 0; e < 4; ++e) d[m][nn][e] = 0.f;

            #pragma unroll
            for (int kt = 0; kt < 8; ++kt) {
                const int koff = kt*32 + q*8;
                uint4 ah[2], al[2];
                uint2 bh[2], bl[2];
                #pragma unroll
                for (int m = 0; m < 2; ++m) ah[m] = Ah[(kt*8 + rw*2 + m)*32 + lane];
                #pragma unroll
                for (int nn = 0; nn < 2; ++nn)
                    bh[nn] = *(const uint2*)(bb + (pair*2 + nn)*(8*BROW) + koff);
                #pragma unroll
                for (int m = 0; m < 2; ++m)
                    #pragma unroll
                    for (int nn = 0; nn < 2; ++nn) mma8(d[m][nn], ah[m], bh[nn]);
                #pragma unroll
                for (int m = 0; m < 2; ++m) al[m] = Al[(kt*8 + rw*2 + m)*32 + lane];
                #pragma unroll
                for (int m = 0; m < 2; ++m)
                    #pragma unroll
                    for (int nn = 0; nn < 2; ++nn) mma8(d[m][nn], al[m], bh[nn]);
                #pragma unroll
                for (int nn = 0; nn < 2; ++nn)
                    bl[nn] = *(const uint2*)(bb + (pair*2 + nn)*(8*BROW) + koff + 256);
                #pragma unroll
                for (int m = 0; m < 2; ++m)
                    #pragma unroll
                    for (int nn = 0; nn < 2; ++nn) mma8(d[m][nn], ah[m], bl[nn]);
            }

            // ---- epilogue for this pair ----
            ull zsp[2], p1p[2];
            const int cbase = cw*32 + 2*q + pair*16;
            #pragma unroll
            for (int nn = 0; nn < 2; ++nn) {
                zsp[nn] = (*(const ull*)(zs2raw + cbase + nn*8)) ^ 0x8000000080000000ULL;
                p1p[nn] = *(const ull*)(p1raw + cbase + nn*8);
            }
            #pragma unroll
            for (int m = 0; m < 2; ++m)
                #pragma unroll
                for (int h = 0; h < 2; ++h) {
                    ull rowc = dup2(nzf2row[m*2+h]);
                    #pragma unroll
                    for (int nn = 0; nn < 2; ++nn) {
                        ull x = pk2(d[m][nn][2*h], d[m][nn][2*h+1]);
                        ADD2(x, x, zsp[nn]);
                        ADD2(x, x, rowc);
                        float2 f = asf2(x);
                        d[m][nn][2*h] = f.x; d[m][nn][2*h+1] = f.y;
                    }
                }

            // row pass
            #pragma unroll
            for (int m = 0; m < 2; ++m)
                #pragma unroll
                for (int h = 0; h < 2; ++h) {
                    const int s = m*2 + h;
                    float bql = bq[s]; int bjl = bj[s];
                    #pragma unroll
                    for (int nn = 0; nn < 2; ++nn) {
                        float fx = d[m][nn][2*h], fy = d[m][nn][2*h+1];
                        int jc = j0 + cbase + nn*8;
                        if (fx > bql) { bql = fx; bjl = jc; }
                        if (fy > bql) { bql = fy; bjl = jc + 1; }
                    }
                    bq[s] = bql; bj[s] = bjl;
                    float ns = fmaf(L2E10, bql, S1g);
                    float rsc = fexp2(shift[s] - ns);
                    shift[s] = ns;
                    { ull rp = dup2(rsc); MUL2(rs2[s], rs2[s], rp); }
                    ull msh = dup2(-ns);
                    #pragma unroll
                    for (int nn = 0; nn < 2; ++nn) {
                        ull c2p = pk2(d[m][nn][2*h], d[m][nn][2*h+1]);
                        ull tp; ADD2(tp, c2p, p1p[nn]);
                        ull tt; FMA2(tt, tp, K.L2, msh);
                        pexp2acc(rs2[s], tt, K);
                    }
                }

            // col pass
            float cmA[2], cmB[2];
            #pragma unroll
            for (int nn = 0; nn < 2; ++nn) { cmA[nn] = -3e38f; cmB[nn] = -3e38f; }
            #pragma unroll
            for (int m = 0; m < 2; ++m)
                #pragma unroll
                for (int h = 0; h < 2; ++h)
                    #pragma unroll
                    for (int nn = 0; nn < 2; ++nn) {
                        cmA[nn] = fmaxf(cmA[nn], d[m][nn][2*h]);
                        cmB[nn] = fmaxf(cmB[nn], d[m][nn][2*h+1]);
                    }
            float shA[2], shB[2]; ull nshp[2]; ull csp[2];
            #pragma unroll
            for (int nn = 0; nn < 2; ++nn) {
                shA[nn] = fmaf(L2E10, cmA[nn], S2g);
                shB[nn] = fmaf(L2E10, cmB[nn], S2g);
                nshp[nn] = pk2(-shA[nn], -shB[nn]);
                csp[nn] = 0ull;
            }
            #pragma unroll
            for (int m = 0; m < 2; ++m)
                #pragma unroll
                for (int h = 0; h < 2; ++h) {
                    ull pr = dup2(p2row[m*2+h]);
                    #pragma unroll
                    for (int nn = 0; nn < 2; ++nn) {
                        ull c2p = pk2(d[m][nn][2*h], d[m][nn][2*h+1]);
                        ull tp; ADD2(tp, c2p, pr);
                        ull tt; FMA2(tt, tp, K.L2, nshp[nn]);
                        pexp2acc(csp[nn], tt, K);
                    }
                }
            float shc[4], csc[4];
            #pragma unroll
            for (int nn = 0; nn < 2; ++nn) {
                float2 f = asf2(csp[nn]);
                shc[2*nn] = shA[nn];   csc[2*nn] = f.x;
                shc[2*nn+1] = shB[nn]; csc[2*nn+1] = f.y;
            }
            #pragma unroll
            for (int mk = 4; mk <= 16; mk <<= 1) {
                #pragma unroll
                for (int s = 0; s < 4; ++s) {
                    float om = __shfl_xor_sync(0xffffffffu, shc[s], mk);
                    float os = __shfl_xor_sync(0xffffffffu, csc[s], mk);
                    if (om > shc[s]) { csc[s] = csc[s]*fexp2(shc[s] - om) + os; shc[s] = om; }
                    else             { csc[s] += os*fexp2(om - shc[s]); }
                }
            }
            if (g == 0) {
                #pragma unroll
                for (int s = 0; s < 4; ++s) {
                    int col = cbase + (s >> 1)*8 + (s & 1);
                    colm[buf*512 + rw*128 + col] = shc[s];
                    colsm[buf*512 + rw*128 + col] = csc[s];
                }
            }
        }
    }

    // ---- final tile's col merge + row merge ----
    __syncthreads();
    if (rw == 0 && g == 0) {
        const int pv = (TPC - 1) & 1;
        const int pj0 = cb*CHUNK + (TPC - 1)*BN;
        const float* cmm = colm + pv*512;
        const float* css = colsm + pv*512;
        #pragma unroll
        for (int s = 0; s < 8; ++s) {
            int col = cw*32 + (s >> 1)*8 + 2*q + (s & 1);
            float m0 = cmm[col], m1 = cmm[128 + col], m2 = cmm[256 + col], m3 = cmm[384 + col];
            float M = fmaxf(fmaxf(m0, m1), fmaxf(m2, m3));
            float S = css[col]*fexp2(m0 - M) + css[128 + col]*fexp2(m1 - M)
                    + css[256 + col]*fexp2(m2 - M) + css[384 + col]*fexp2(m3 - M);
            g_c_m[(pj0 + col)*NRB + rb] = M;
            g_c_s[(pj0 + col)*NRB + rb] = S;
        }
    }

    float rss[4];
    #pragma unroll
    for (int s = 0; s < 4; ++s) { float2 f = asf2(rs2[s]); rss[s] = f.x + f.y; }
    #pragma unroll
    for (int mk = 1; mk <= 2; mk <<= 1) {
        #pragma unroll
        for (int s = 0; s < 4; ++s) {
            float om = __shfl_xor_sync(0xffffffffu, shift[s], mk);
            float os = __shfl_xor_sync(0xffffffffu, rss[s], mk);
            float ob = __shfl_xor_sync(0xffffffffu, bq[s], mk);
            int   oj = __shfl_xor_sync(0xffffffffu, bj[s], mk);
            if (om > shift[s]) { rss[s] = rss[s]*fexp2(shift[s] - om) + os; shift[s] = om; }
            else               { rss[s] += os*fexp2(om - shift[s]); }
            if (ob > bq[s] || (ob == bq[s] && oj < bj[s])) { bq[s] = ob; bj[s] = oj; }
        }
    }
    if (q == 0) {
        #pragma unroll
        for (int s = 0; s < 4; ++s) {
            int row = (rw*2 + (s >> 1))*16 + (s & 1)*8 + g;
            rowm[row*4 + cw] = shift[s];
            rowss[row*4 + cw] = rss[s];
            rowb[row*4 + cw] = bq[s];
            rowj[row*4 + cw] = bj[s];
        }
    }
    __syncthreads();
    if (tid < 128) {
        float4 mv = *(const float4*)(rowm + tid*4);
        float4 sv = *(const float4*)(rowss + tid*4);
        float M = fmaxf(fmaxf(mv.x, mv.y), fmaxf(mv.z, mv.w));
        float S = sv.x*fexp2(mv.x - M) + sv.y*fexp2(mv.y - M)
                + sv.z*fexp2(mv.z - M) + sv.w*fexp2(mv.w - M);
        float bqv = -3e38f; int bjv = 0x7fffffff;
        #pragma unroll
        for (int c = 0; c < 4; ++c) {
            float bb2 = rowb[tid*4 + c]; int jj = rowj[tid*4 + c];
            if (bb2 > bqv || (bb2 == bqv && jj < bjv)) { bqv = bb2; bjv = jj; }
        }
        g_r_m [(i0 + tid)*NCB + cb] = M;
        g_r_s [(i0 + tid)*NCB + cb] = S;
        g_r_bc[(i0 + tid)*NCB + cb] = bqv;
        g_r_bj[(i0 + tid)*NCB + cb] = bjv;
    }
}

// ---------------- k3: two-pass merges, vectorized loads ----------------
__global__ void k3() {
    int i = blockIdx.x*blockDim.x + threadIdx.x;
    {
        float4 mv = *(const float4*)(g_r_m + i*4);
        float4 sv = *(const float4*)(g_r_s + i*4);
        float4 bv = *(const float4*)(g_r_bc + i*4);
        int4   jv = *(const int4*)  (g_r_bj + i*4);
        float M = fmaxf(fmaxf(mv.x, mv.y), fmaxf(mv.z, mv.w));
        float S = sv.x*fexp2(mv.x - M) + sv.y*fexp2(mv.y - M)
                + sv.z*fexp2(mv.z - M) + sv.w*fexp2(mv.w - M);
        g_lse1[i] = LN2*(M + log2f(S)) - logf((float)Nn);
        float bqv = bv.x; int bjv = jv.x;
        if (bv.y > bqv || (bv.y == bqv && jv.y < bjv)) { bqv = bv.y; bjv = jv.y; }
        if (bv.z > bqv || (bv.z == bqv && jv.z < bjv)) { bqv = bv.z; bjv = jv.z; }
        if (bv.w > bqv || (bv.w == bqv && jv.w < bjv)) { bqv = bv.w; bjv = jv.w; }
        g_idx[i] = bjv;
    }
    {
        float4 mv[8];
        #pragma unroll
        for (int k = 0; k < 8; ++k) mv[k] = *(const float4*)(g_c_m + i*32 + k*4);
        float M = -3e38f;
        #pragma unroll
        for (int k = 0; k < 8; ++k)
            M = fmaxf(M, fmaxf(fmaxf(mv[k].x, mv[k].y), fmaxf(mv[k].z, mv[k].w)));
        float S = 0.f;
        #pragma unroll
        for (int k = 0; k < 8; ++k) {
            float4 sv = *(const float4*)(g_c_s + i*32 + k*4);
            S += sv.x*fexp2(mv[k].x - M) + sv.y*fexp2(mv[k].y - M)
               + sv.z*fexp2(mv[k].z - M) + sv.w*fexp2(mv[k].w - M);
        }
        g_lse2[i] = LN2*(M + log2f(S));
    }
}

// ---------------- k45 ----------------
__global__ void k45(const float* __restrict__ z, const float* __restrict__ codebook,
                    float* __restrict__ out) {
    __shared__ int cnt[Nn];
    __shared__ double wred[8*5];
    int tid = threadIdx.x;
    int blk = blockIdx.x;
    if (blk == 0) {
        double v0 = 0, v1 = 0, v2 = 0, v3 = 0;
        for (int i = tid; i < Nn; i += 256) {
            v0 += (double)g_lse1[i];
            v1 += (double)g_phi1[i];
            v2 += (double)g_lse2[i];
            v3 += (double)g_phi2[i];
        }
        for (int i = tid; i < Nn; i += 256) cnt[i] = 0;
        __syncthreads();
        for (int i = tid; i < Nn; i += 256) atomicAdd(&cnt[g_idx[i]], 1);
        __syncthreads();
        double v4 = 0;
        for (int i = tid; i < Nn; i += 256) {
            int c = cnt[i];
            if (c > 0) { float em = (float)c / (float)Nn; v4 += (double)(em * logf(em + 1e-10f)); }
        }
        double vals[5] = {v0, v1, v2, v3, v4};
        int lane = tid & 31, warp = tid >> 5;
        #pragma unroll
        for (int v = 0; v < 5; ++v) {
            double x = vals[v];
            #pragma unroll
            for (int o = 16; o > 0; o >>= 1) x += __shfl_xor_sync(0xffffffffu, x, o);
            if (lane == 0) wred[warp*5 + v] = x;
        }
        __syncthreads();
        if (tid == 0) {
            double t[5] = {0, 0, 0, 0, 0};
            for (int w = 0; w < 8; ++w)
                for (int v = 0; v < 5; ++v) t[v] += wred[w*5 + v];
            double n = (double)Nn;
            double loss1 = (-0.1*t[0] + t[1]) / n;
            double loss2 = (-0.1*t[2]) / n + 0.1*log(n) + t[3]/n;
            out[2*OUTPLANE]     = (float)(0.25*(loss1 + loss2));
            out[2*OUTPLANE + 1] = (float)exp(-t[4]);
        }
        return;
    }
    int o = (blk - 1)*256 + tid;
    int w = o & 15, h = (o >> 4) & 15, c = (o >> 8) & 63, b = o >> 14;
    int i = (h*16 + w)*16 + b;
    out[o] = codebook[(g_idx[i] >> 3)*(2*Dd) + c];
    out[OUTPLANE + o] = z[o];
}

// ---------------- launch ----------------
extern "C" void kernel_launch(void* const* d_in, const int* in_sizes, int n_in,
                              void* d_out, int out_size) {
    const float* z        = (const float*)d_in[0];
    const float* codebook = (const float*)d_in[1];
    const float* w1       = (const float*)d_in[3];
    const float* b1       = (const float*)d_in[4];
    const float* w2       = (const float*)d_in[5];
    const float* b2       = (const float*)d_in[6];
    const float* noise    = (const float*)d_in[7];
    float* out = (float*)d_out;

    cudaFuncSetAttribute(k2, cudaFuncAttributeMaxDynamicSharedMemorySize, SMEM_BYTES);

    k0tr<<<257, 256>>>(z, w1, b1, w2, b2);
    k1<<<Nn/4, 128>>>(codebook, noise);
    {
        dim3 g(NRB, NCB);
        k2<<<g, 512, SMEM_BYTES>>>();
    }
    k3<<<Nn/256, 256>>>();
    k45<<<1025, 256>>>(z, codebook, out);
}

// round 14
// speedup vs baseline: 1.2174x; 1.2174x over previous
#include <cuda_runtime.h>
#include <math.h>
#include <stdint.h>

// ---------------- problem constants ----------------
#define Nn 4096
#define Dd 64
#define HKk 256
#define BM 128
#define BN 128
#define NRB 32
#define NCB 4
#define CHUNK 1024
#define TPC 8
#define OUTPLANE 262144
#define L2E10 14.426950408889634f
#define LN2 0.6931471805599453f

typedef unsigned long long ull;

// ---------------- static device scratch ----------------
__device__ float g_zf[Nn*Dd];
__device__ float g_zf_hi[Nn*Dd], g_zf_lo[Nn*Dd];   // scaled by 2 (A side)
__device__ float g_zsP[Nn*128];                    // B side: [row][hi 64 perm | lo 64 perm]
__device__ float g_zf2[Nn], g_zs2[Nn], g_phi1[Nn], g_phi2[Nn];
__device__ float g_w1m[Dd], g_w2m[Dd], g_b1m, g_b2m;
__device__ unsigned g_aph1, g_aph2;
// transposed partials: rows [i][cb], cols [col][rb]
__device__ float g_r_m[Nn*NCB], g_r_s[Nn*NCB], g_r_bc[Nn*NCB];
__device__ int   g_r_bj[Nn*NCB];
__device__ float g_c_m[Nn*NRB], g_c_s[Nn*NRB];
__device__ int   g_idx[Nn];
__device__ float g_lse1[Nn], g_lse2[Nn];

// ---------------- f32x2 packed helpers ----------------
#define FMA2(d,a,b,c) asm("fma.rn.f32x2 %0, %1, %2, %3;" : "=l"(d) : "l"(a), "l"(b), "l"(c))
#define ADD2(d,a,b)   asm("add.rn.f32x2 %0, %1, %2;"     : "=l"(d) : "l"(a), "l"(b))
#define MUL2(d,a,b)   asm("mul.rn.f32x2 %0, %1, %2;"     : "=l"(d) : "l"(a), "l"(b))

__device__ __forceinline__ ull dup2(float x) {
    ull r; asm("mov.b64 %0, {%1, %1};" : "=l"(r) : "f"(x)); return r;
}
__device__ __forceinline__ ull pk2(float lo, float hi) {
    ull r; asm("mov.b64 %0, {%1, %2};" : "=l"(r) : "f"(lo), "f"(hi)); return r;
}
__device__ __forceinline__ float2 asf2(ull v) {
    float2 f; asm("mov.b64 {%0, %1}, %2;" : "=f"(f.x), "=f"(f.y) : "l"(v)); return f;
}

struct PC { ull MAG, NMAG, NEG1, D3, D2, D1, ONE, L2; };
__device__ __forceinline__ PC make_pc() {
    PC K;
    K.MAG  = dup2(12582912.0f);
    K.NMAG = dup2(-12582912.0f);
    K.NEG1 = dup2(-1.0f);
    K.D3   = dup2(0.0558367f);
    K.D2   = dup2(0.2414282f);
    K.D1   = dup2(0.6931472f);
    K.ONE  = dup2(1.0f);
    K.L2   = dup2(L2E10);
    return K;
}

// acc += exp2(t) (deg-3; args <= 0; underflow clamps to 0)
__device__ __forceinline__ void pexp2acc(ull &acc, ull t, const PC& K) {
    ull tb; ADD2(tb, t, K.MAG);
    ull rr; ADD2(rr, tb, K.NMAG);
    ull f;  FMA2(f, rr, K.NEG1, t);
    ull p = K.D3;
    FMA2(p, p, f, K.D2);
    FMA2(p, p, f, K.D1);
    FMA2(p, p, f, K.ONE);
    int elo = (int)(unsigned)tb         + (127 - 0x4B400000);
    int ehi = (int)(unsigned)(tb >> 32) + (127 - 0x4B400000);
    elo = elo < 0 ? 0 : elo;
    ehi = ehi < 0 ? 0 : ehi;
    ull sc = pk2(__int_as_float(elo << 23), __int_as_float(ehi << 23));
    FMA2(acc, p, sc, acc);
}

// scalar exp2 (deg-5, merges only)
__device__ __forceinline__ float fexp2(float x) {
    float t  = fmaxf(x, -126.0f);
    float tb = t + 12582912.0f;
    int   ni = __float_as_int(tb);
    float r  = tb - 12582912.0f;
    float f  = t - r;
    float p  = 0.00133335581f;
    p = fmaf(p, f, 0.00961812910f);
    p = fmaf(p, f, 0.0555041087f);
    p = fmaf(p, f, 0.240226507f);
    p = fmaf(p, f, 0.693147180f);
    p = fmaf(p, f, 1.0f);
    float sc = __int_as_float((ni + (127 - 0x4B400000)) << 23);
    return p * sc;
}

__device__ __forceinline__ unsigned fenc(float f) {
    unsigned u = __float_as_uint(f);
    return (u & 0x80000000u) ? ~u : (u | 0x80000000u);
}
__device__ __forceinline__ float fdec(unsigned u) {
    return (u & 0x80000000u) ? __uint_as_float(u & 0x7fffffffu) : __uint_as_float(~u);
}

__device__ __forceinline__ float tf32_hi(float x) {
    uint32_t h; asm("cvt.rna.tf32.f32 %0, %1;" : "=r"(h) : "f"(x));
    return __uint_as_float(h);
}

// mma.sync m16n8k8 tf32
__device__ __forceinline__ void mma8(float* d, const uint4& a, const uint2& b) {
    asm("mma.sync.aligned.m16n8k8.row.col.f32.tf32.tf32.f32 "
        "{%0,%1,%2,%3}, {%4,%5,%6,%7}, {%8,%9}, {%0,%1,%2,%3};"
        : "+f"(d[0]), "+f"(d[1]), "+f"(d[2]), "+f"(d[3])
        : "r"(a.x), "r"(a.y), "r"(a.z), "r"(a.w), "r"(b.x), "r"(b.y));
}

// ---------------- cp.async ----------------
#define CPASYNC16(s, g) asm volatile("cp.async.cg.shared.global [%0], [%1], 16;" :: "r"(s), "l"(g))
#define CPASYNC4(s, g)  asm volatile("cp.async.ca.shared.global [%0], [%1], 4;"  :: "r"(s), "l"(g))
#define CP_COMMIT       asm volatile("cp.async.commit_group;" ::: "memory")
#define CP_WAIT(n)      asm volatile("cp.async.wait_group %0;" :: "n"(n) : "memory")

__device__ __forceinline__ uint32_t smem_u32(const void* p) {
    uint32_t a;
    asm("{ .reg .u64 t; cvta.to.shared.u64 t, %1; cvt.u32.u64 %0, t; }" : "=r"(a) : "l"(p));
    return a;
}

// ---------------- smem layout (bytes) ----------------
#define BROW 544
#define BBUF (128*BROW)
#define OFF_A    0
#define OFF_ALO  32768
#define OFF_B    65536
#define OFF_ZS2(b) (204800 + (b)*512)
#define OFF_P1(b)  (205824 + (b)*512)
#define OFF_NZF2 206848
#define OFF_P2   207360
#define OFF_COLM 207872
#define OFF_COLS 211968
#define OFF_ROWM 216064
#define OFF_ROWS 218112
#define OFF_ROWB 220160
#define OFF_ROWJ 222208
#define SMEM_BYTES (224256 + 1024)

// ---------------- k0tr ----------------
__global__ void k0tr(const float* __restrict__ z,
                     const float* __restrict__ w1, const float* __restrict__ b1,
                     const float* __restrict__ w2, const float* __restrict__ b2) {
    __shared__ float tsh[32][33];
    int tid = threadIdx.x;
    int blk = blockIdx.x;
    if (blk == 256) {
        int d = tid >> 2, part = tid & 3;
        float s1 = 0.f, s2 = 0.f;
        for (int k = part*64; k < part*64 + 64; ++k) {
            s1 += w1[d*HKk + k]; s2 += w2[d*HKk + k];
        }
        s1 += __shfl_xor_sync(0xffffffffu, s1, 1);
        s1 += __shfl_xor_sync(0xffffffffu, s1, 2);
        s2 += __shfl_xor_sync(0xffffffffu, s2, 1);
        s2 += __shfl_xor_sync(0xffffffffu, s2, 2);
        if (part == 0) { g_w1m[d] = s1 / (float)HKk; g_w2m[d] = s2 / (float)HKk; }
        if (tid < 64) {
            const float* bb = (tid < 32) ? b1 : b2;
            int l = tid & 31;
            float s = 0.f;
            for (int k = l; k < HKk; k += 32) s += bb[k];
            #pragma unroll
            for (int o = 16; o > 0; o >>= 1) s += __shfl_xor_sync(0xffffffffu, s, o);
            if (l == 0) {
                if (tid < 32) { g_b1m = s / (float)HKk; g_aph1 = 0u; }
                else          { g_b2m = s / (float)HKk; g_aph2 = 0u; }
            }
        }
        return;
    }
    int bx = blk & 7, by = blk >> 3;
    int tx = tid & 31, ty = tid >> 5;
    int x = bx*32 + tx;
    #pragma unroll
    for (int q = 0; q < 4; ++q) {
        int row = by*32 + ty + q*8;
        tsh[ty + q*8][tx] = z[row*256 + x];
    }
    __syncthreads();
    #pragma unroll
    for (int q = 0; q < 4; ++q) {
        int col = bx*32 + ty + q*8;
        int row = by*32 + tx;
        g_zf[col*1024 + row] = tsh[tx][ty + q*8];
    }
}

// ---------------- k1 ----------------
__global__ void k1(const float* __restrict__ codebook, const float* __restrict__ noise) {
    int warp = threadIdx.x >> 5, lane = threadIdx.x & 31;
    int row = blockIdx.x*4 + warp;
    const float* crow = codebook + (row >> 3) * (2*Dd);
    const float* nrow = noise + row*Dd;
    const float* frow = g_zf + row*Dd;
    float zs2 = 0.f, p1 = 0.f, zf2 = 0.f, p2 = 0.f;
    #pragma unroll
    for (int q = 0; q < 2; ++q) {
        int d = lane + q*32;
        float mu  = crow[d];
        float cov = expf(crow[Dd + d]);
        float zs  = mu + cov * nrow[d];
        float zh = tf32_hi(zs);
        int pos = ((d >> 3) << 3) + ((d & 3) << 1) + ((d >> 2) & 1);
        g_zsP[row*128 + pos]      = zh;
        g_zsP[row*128 + 64 + pos] = tf32_hi(zs - zh);
        zs2 += zs*zs;
        p1  += zs * g_w1m[d];
        float zf = frow[d];
        float fh = tf32_hi(zf);
        g_zf_hi[row*Dd + d] = 2.0f * fh;
        g_zf_lo[row*Dd + d] = 2.0f * tf32_hi(zf - fh);
        zf2 += zf*zf;
        p2  += zf * g_w2m[d];
    }
    #pragma unroll
    for (int o = 16; o > 0; o >>= 1) {
        zs2 += __shfl_xor_sync(0xffffffffu, zs2, o);
        p1  += __shfl_xor_sync(0xffffffffu, p1,  o);
        zf2 += __shfl_xor_sync(0xffffffffu, zf2, o);
        p2  += __shfl_xor_sync(0xffffffffu, p2,  o);
    }
    if (lane == 0) {
        float phi1 = p1 + g_b1m, phi2 = p2 + g_b2m;
        g_zs2[row] = zs2;  g_phi1[row] = phi1;
        g_zf2[row] = zf2;  g_phi2[row] = phi2;
        atomicMax(&g_aph1, fenc(phi1));
        atomicMax(&g_aph2, fenc(phi2));
    }
}

// ---------------- k2: R10 monolithic GEMM + safe pipeline order + wide merges ----------------
__global__ void __launch_bounds__(512, 1) k2() {
    extern __shared__ char smem_raw[];
    char* sb = (char*)(((uintptr_t)smem_raw + 1023) & ~(uintptr_t)1023);
    const uint32_t sba = smem_u32(sb);

    const int tid  = threadIdx.x;
    const int lane = tid & 31, wid = tid >> 5;
    const int rw = wid >> 2, cw = wid & 3;
    const int q  = lane & 3,  g  = lane >> 2;
    const int rb = blockIdx.x, cb = blockIdx.y;
    const int i0 = rb * BM;
    const float S1g = L2E10 * fdec(g_aph1);
    const float S2g = L2E10 * fdec(g_aph2);
    const PC K = make_pc();

    float* nzf2s = (float*)(sb + OFF_NZF2);
    float* p2s   = (float*)(sb + OFF_P2);
    float* colm  = (float*)(sb + OFF_COLM);
    float* colsm = (float*)(sb + OFF_COLS);
    float* rowm  = (float*)(sb + OFF_ROWM);
    float* rowss = (float*)(sb + OFF_ROWS);
    float* rowb  = (float*)(sb + OFF_ROWB);
    int*   rowj  = (int*)  (sb + OFF_ROWJ);

    // ---- prologue: prefetch tile 0 (buf 0) ----
    {
        const int j0 = cb*CHUNK;
        for (int idx = tid; idx < 4096; idx += 512) {
            int row = idx >> 5, ch = idx & 31;
            CPASYNC16(sba + OFF_B + row*BROW + ch*16, g_zsP + (j0 + row)*128 + ch*4);
        }
        if (tid < 128) {
            CPASYNC4(sba + OFF_ZS2(0) + tid*4, g_zs2 + j0 + tid);
            CPASYNC4(sba + OFF_P1(0)  + tid*4, g_phi1 + j0 + tid);
        }
        CP_COMMIT;
    }

    // ---- stage A fragments + row scalars ----
    {
        float4* Ah = (float4*)(sb + OFF_A);
        float4* Al = (float4*)(sb + OFF_ALO);
        for (int t2 = tid; t2 < 2048; t2 += 512) {
            int kt = t2 >> 8, mt = (t2 >> 5) & 7, l = t2 & 31;
            int r0 = (i0 + mt*16 + (l >> 2)) * 64;
            int r8 = r0 + 8*64;
            int c0 = kt*8 + (l & 3);
            float4 v;
            v.x = g_zf_hi[r0 + c0];
            v.y = g_zf_hi[r8 + c0];
            v.z = g_zf_hi[r0 + c0 + 4];
            v.w = g_zf_hi[r8 + c0 + 4];
            Ah[t2] = v;
            v.x = g_zf_lo[r0 + c0];
            v.y = g_zf_lo[r8 + c0];
            v.z = g_zf_lo[r0 + c0 + 4];
            v.w = g_zf_lo[r8 + c0 + 4];
            Al[t2] = v;
        }
        if (tid < 128) {
            nzf2s[tid] = -g_zf2[i0 + tid];
            p2s[tid]   = g_phi2[i0 + tid];
        }
    }
    __syncthreads();

    float nzf2row[4], p2row[4];
    #pragma unroll
    for (int m = 0; m < 2; ++m)
        #pragma unroll
        for (int h = 0; h < 2; ++h) {
            int row = (rw*2 + m)*16 + h*8 + g;
            nzf2row[m*2+h] = nzf2s[row];
            p2row[m*2+h]   = p2s[row];
        }

    float bq[4], shift[4]; int bj[4]; ull rs2[4];
    #pragma unroll
    for (int s = 0; s < 4; ++s) { bq[s] = -3e38f; shift[s] = -1e30f; bj[s] = 0x7fffffff; rs2[s] = 0ull; }

    const uint4* Ah = (const uint4*)(sb + OFF_A);
    const uint4* Al = (const uint4*)(sb + OFF_ALO);
    const int browoff = (cw*32 + g)*BROW;

    for (int t = 0; t < TPC; ++t) {
        const int buf = t & 1;
        const int j0 = cb*CHUNK + t*BN;

        CP_WAIT(0);            // tile t data arrived
        __syncthreads();       // all warps done with body t-1; safe to overwrite other buffer

        // ---- merge previous tile's col partials (128 threads, 1 col each) ----
        if (t > 0 && rw == 0) {
            const int pv = (t - 1) & 1;
            const int pj0 = cb*CHUNK + (t - 1)*BN;
            const float* cmm = colm + pv*512;
            const float* css = colsm + pv*512;
            int col = cw*32 + lane;
            float m0 = cmm[col], m1 = cmm[128 + col], m2 = cmm[256 + col], m3 = cmm[384 + col];
            float M = fmaxf(fmaxf(m0, m1), fmaxf(m2, m3));
            float S = css[col]*fexp2(m0 - M) + css[128 + col]*fexp2(m1 - M)
                    + css[256 + col]*fexp2(m2 - M) + css[384 + col]*fexp2(m3 - M);
            g_c_m[(pj0 + col)*NRB + rb] = M;
            g_c_s[(pj0 + col)*NRB + rb] = S;
        }

        // ---- prefetch tile t+1 ----
        if (t + 1 < TPC) {
            const int nb = (t + 1) & 1;
            const int nj0 = cb*CHUNK + (t + 1)*BN;
            for (int idx = tid; idx < 4096; idx += 512) {
                int row = idx >> 5, ch = idx & 31;
                CPASYNC16(sba + OFF_B + nb*BBUF + row*BROW + ch*16, g_zsP + (nj0 + row)*128 + ch*4);
            }
            if (tid < 128) {
                CPASYNC4(sba + OFF_ZS2(nb) + tid*4, g_zs2 + nj0 + tid);
                CPASYNC4(sba + OFF_P1(nb)  + tid*4, g_phi1 + nj0 + tid);
            }
            CP_COMMIT;
        }

        const char* bb = sb + OFF_B + buf*BBUF + browoff;

        // ---- GEMM (monolithic, 4 n-frags) ----
        float d[2][4][4];
        #pragma unroll
        for (int m = 0; m < 2; ++m)
            #pragma unroll
            for (int n = 0; n < 4; ++n)
                #pragma unroll
                for (int e = 0; e < 4; ++e) d[m][n][e] = 0.f;

        #pragma unroll
        for (int kt = 0; kt < 8; ++kt) {
            const int koff = kt*32 + q*8;
            uint4 ah[2], al[2];
            uint2 bh[4], bl[4];
            #pragma unroll
            for (int m = 0; m < 2; ++m) ah[m] = Ah[(kt*8 + rw*2 + m)*32 + lane];
            #pragma unroll
            for (int n = 0; n < 4; ++n) bh[n] = *(const uint2*)(bb + n*(8*BROW) + koff);
            #pragma unroll
            for (int m = 0; m < 2; ++m)
                #pragma unroll
                for (int n = 0; n < 4; ++n) mma8(d[m][n], ah[m], bh[n]);
            #pragma unroll
            for (int m = 0; m < 2; ++m) al[m] = Al[(kt*8 + rw*2 + m)*32 + lane];
            #pragma unroll
            for (int m = 0; m < 2; ++m)
                #pragma unroll
                for (int n = 0; n < 4; ++n) mma8(d[m][n], al[m], bh[n]);
            #pragma unroll
            for (int n = 0; n < 4; ++n) bl[n] = *(const uint2*)(bb + n*(8*BROW) + koff + 256);
            #pragma unroll
            for (int m = 0; m < 2; ++m)
                #pragma unroll
                for (int n = 0; n < 4; ++n) mma8(d[m][n], ah[m], bl[n]);
        }

        // ---- c2 = D - zs2 - zf2 ----
        const float* zs2raw = (const float*)(sb + OFF_ZS2(buf));
        const float* p1raw  = (const float*)(sb + OFF_P1(buf));
        ull zsp[4], p1p[4];
        const int cbase = cw*32 + 2*q;
        #pragma unroll
        for (int n = 0; n < 4; ++n) {
            zsp[n] = (*(const ull*)(zs2raw + cbase + n*8)) ^ 0x8000000080000000ULL;
            p1p[n] = *(const ull*)(p1raw + cbase + n*8);
        }
        #pragma unroll
        for (int m = 0; m < 2; ++m)
            #pragma unroll
            for (int h = 0; h < 2; ++h) {
                ull rowc = dup2(nzf2row[m*2+h]);
                #pragma unroll
                for (int n = 0; n < 4; ++n) {
                    ull x = pk2(d[m][n][2*h], d[m][n][2*h+1]);
                    ADD2(x, x, zsp[n]);
                    ADD2(x, x, rowc);
                    float2 f = asf2(x);
                    d[m][n][2*h] = f.x; d[m][n][2*h+1] = f.y;
                }
            }

        // ---- row pass ----
        #pragma unroll
        for (int m = 0; m < 2; ++m)
            #pragma unroll
            for (int h = 0; h < 2; ++h) {
                const int s = m*2 + h;
                float bql = bq[s]; int bjl = bj[s];
                #pragma unroll
                for (int n = 0; n < 4; ++n) {
                    float fx = d[m][n][2*h], fy = d[m][n][2*h+1];
                    int jc = j0 + cw*32 + n*8 + 2*q;
                    if (fx > bql) { bql = fx; bjl = jc; }
                    if (fy > bql) { bql = fy; bjl = jc + 1; }
                }
                bq[s] = bql; bj[s] = bjl;
                float ns = fmaf(L2E10, bql, S1g);
                float rsc = fexp2(shift[s] - ns);
                shift[s] = ns;
                { ull rp = dup2(rsc); MUL2(rs2[s], rs2[s], rp); }
                ull msh = dup2(-ns);
                #pragma unroll
                for (int n = 0; n < 4; ++n) {
                    ull c2p = pk2(d[m][n][2*h], d[m][n][2*h+1]);
                    ull tp; ADD2(tp, c2p, p1p[n]);
                    ull tt; FMA2(tt, tp, K.L2, msh);
                    pexp2acc(rs2[s], tt, K);
                }
            }

        // ---- col pass ----
        float cmA[4], cmB[4];
        #pragma unroll
        for (int n = 0; n < 4; ++n) { cmA[n] = -3e38f; cmB[n] = -3e38f; }
        #pragma unroll
        for (int m = 0; m < 2; ++m)
            #pragma unroll
            for (int h = 0; h < 2; ++h)
                #pragma unroll
                for (int n = 0; n < 4; ++n) {
                    cmA[n] = fmaxf(cmA[n], d[m][n][2*h]);
                    cmB[n] = fmaxf(cmB[n], d[m][n][2*h+1]);
                }
        float shA[4], shB[4]; ull nshp[4]; ull csp[4];
        #pragma unroll
        for (int n = 0; n < 4; ++n) {
            shA[n] = fmaf(L2E10, cmA[n], S2g);
            shB[n] = fmaf(L2E10, cmB[n], S2g);
            nshp[n] = pk2(-shA[n], -shB[n]);
            csp[n] = 0ull;
        }
        #pragma unroll
        for (int m = 0; m < 2; ++m)
            #pragma unroll
            for (int h = 0; h < 2; ++h) {
                ull pr = dup2(p2row[m*2+h]);
                #pragma unroll
                for (int n = 0; n < 4; ++n) {
                    ull c2p = pk2(d[m][n][2*h], d[m][n][2*h+1]);
                    ull tp; ADD2(tp, c2p, pr);
                    ull tt; FMA2(tt, tp, K.L2, nshp[n]);
                    pexp2acc(csp[n], tt, K);
                }
            }
        float shc[8], csc[8];
        #pragma unroll
        for (int n = 0; n < 4; ++n) {
            float2 f = asf2(csp[n]);
            shc[2*n] = shA[n];   csc[2*n] = f.x;
            shc[2*n+1] = shB[n]; csc[2*n+1] = f.y;
        }
        #pragma unroll
        for (int mk = 4; mk <= 16; mk <<= 1) {
            #pragma unroll
            for (int s = 0; s < 8; ++s) {
                float om = __shfl_xor_sync(0xffffffffu, shc[s], mk);
                float os = __shfl_xor_sync(0xffffffffu, csc[s], mk);
                if (om > shc[s]) { csc[s] = csc[s]*fexp2(shc[s] - om) + os; shc[s] = om; }
                else             { csc[s] += os*fexp2(om - shc[s]); }
            }
        }
        if (g == 0) {
            #pragma unroll
            for (int s = 0; s < 8; ++s) {
                int col = cw*32 + (s >> 1)*8 + 2*q + (s & 1);
                colm[buf*512 + rw*128 + col] = shc[s];
                colsm[buf*512 + rw*128 + col] = csc[s];
            }
        }
    }

    // ---- final tile's col merge (128 threads) + row merge ----
    __syncthreads();
    if (rw == 0) {
        const int pv = (TPC - 1) & 1;
        const int pj0 = cb*CHUNK + (TPC - 1)*BN;
        const float* cmm = colm + pv*512;
        const float* css = colsm + pv*512;
        int col = cw*32 + lane;
        float m0 = cmm[col], m1 = cmm[128 + col], m2 = cmm[256 + col], m3 = cmm[384 + col];
        float M = fmaxf(fmaxf(m0, m1), fmaxf(m2, m3));
        float S = css[col]*fexp2(m0 - M) + css[128 + col]*fexp2(m1 - M)
                + css[256 + col]*fexp2(m2 - M) + css[384 + col]*fexp2(m3 - M);
        g_c_m[(pj0 + col)*NRB + rb] = M;
        g_c_s[(pj0 + col)*NRB + rb] = S;
    }

    float rss[4];
    #pragma unroll
    for (int s = 0; s < 4; ++s) { float2 f = asf2(rs2[s]); rss[s] = f.x + f.y; }
    #pragma unroll
    for (int mk = 1; mk <= 2; mk <<= 1) {
        #pragma unroll
        for (int s = 0; s < 4; ++s) {
            float om = __shfl_xor_sync(0xffffffffu, shift[s], mk);
            float os = __shfl_xor_sync(0xffffffffu, rss[s], mk);
            float ob = __shfl_xor_sync(0xffffffffu, bq[s], mk);
            int   oj = __shfl_xor_sync(0xffffffffu, bj[s], mk);
            if (om > shift[s]) { rss[s] = rss[s]*fexp2(shift[s] - om) + os; shift[s] = om; }
            else               { rss[s] += os*fexp2(om - shift[s]); }
            if (ob > bq[s] || (ob == bq[s] && oj < bj[s])) { bq[s] = ob; bj[s] = oj; }
        }
    }
    if (q == 0) {
        #pragma unroll
        for (int s = 0; s < 4; ++s) {
            int row = (rw*2 + (s >> 1))*16 + (s & 1)*8 + g;
            rowm[row*4 + cw] = shift[s];
            rowss[row*4 + cw] = rss[s];
            rowb[row*4 + cw] = bq[s];
            rowj[row*4 + cw] = bj[s];
        }
    }
    __syncthreads();
    if (tid < 128) {
        float4 mv = *(const float4*)(rowm + tid*4);
        float4 sv = *(const float4*)(rowss + tid*4);
        float M = fmaxf(fmaxf(mv.x, mv.y), fmaxf(mv.z, mv.w));
        float S = sv.x*fexp2(mv.x - M) + sv.y*fexp2(mv.y - M)
                + sv.z*fexp2(mv.z - M) + sv.w*fexp2(mv.w - M);
        float bqv = -3e38f; int bjv = 0x7fffffff;
        #pragma unroll
        for (int c = 0; c < 4; ++c) {
            float bb2 = rowb[tid*4 + c]; int jj = rowj[tid*4 + c];
            if (bb2 > bqv || (bb2 == bqv && jj < bjv)) { bqv = bb2; bjv = jj; }
        }
        g_r_m [(i0 + tid)*NCB + cb] = M;
        g_r_s [(i0 + tid)*NCB + cb] = S;
        g_r_bc[(i0 + tid)*NCB + cb] = bqv;
        g_r_bj[(i0 + tid)*NCB + cb] = bjv;
    }
}

// ---------------- k3: split row/col merges across 32 blocks ----------------
__global__ void k3() {
    int blk = blockIdx.x, tid = threadIdx.x;
    if (blk < 16) {
        int i = blk*256 + tid;
        float4 mv = *(const float4*)(g_r_m + i*4);
        float4 sv = *(const float4*)(g_r_s + i*4);
        float4 bv = *(const float4*)(g_r_bc + i*4);
        int4   jv = *(const int4*)  (g_r_bj + i*4);
        float M = fmaxf(fmaxf(mv.x, mv.y), fmaxf(mv.z, mv.w));
        float S = sv.x*fexp2(mv.x - M) + sv.y*fexp2(mv.y - M)
                + sv.z*fexp2(mv.z - M) + sv.w*fexp2(mv.w - M);
        g_lse1[i] = LN2*(M + log2f(S)) - logf((float)Nn);
        float bqv = bv.x; int bjv = jv.x;
        if (bv.y > bqv || (bv.y == bqv && jv.y < bjv)) { bqv = bv.y; bjv = jv.y; }
        if (bv.z > bqv || (bv.z == bqv && jv.z < bjv)) { bqv = bv.z; bjv = jv.z; }
        if (bv.w > bqv || (bv.w == bqv && jv.w < bjv)) { bqv = bv.w; bjv = jv.w; }
        g_idx[i] = bjv;
    } else {
        int i = (blk - 16)*256 + tid;
        float4 mv[8];
        #pragma unroll
        for (int k = 0; k < 8; ++k) mv[k] = *(const float4*)(g_c_m + i*32 + k*4);
        float M = -3e38f;
        #pragma unroll
        for (int k = 0; k < 8; ++k)
            M = fmaxf(M, fmaxf(fmaxf(mv[k].x, mv[k].y), fmaxf(mv[k].z, mv[k].w)));
        float S = 0.f;
        #pragma unroll
        for (int k = 0; k < 8; ++k) {
            float4 sv = *(const float4*)(g_c_s + i*32 + k*4);
            S += sv.x*fexp2(mv[k].x - M) + sv.y*fexp2(mv[k].y - M)
               + sv.z*fexp2(mv[k].z - M) + sv.w*fexp2(mv[k].w - M);
        }
        g_lse2[i] = LN2*(M + log2f(S));
    }
}

// ---------------- k45 ----------------
__global__ void k45(const float* __restrict__ z, const float* __restrict__ codebook,
                    float* __restrict__ out) {
    __shared__ int cnt[Nn];
    __shared__ double wred[8*5];
    int tid = threadIdx.x;
    int blk = blockIdx.x;
    if (blk == 0) {
        double v0 = 0, v1 = 0, v2 = 0, v3 = 0;
        for (int i = tid; i < Nn; i += 256) {
            v0 += (double)g_lse1[i];
            v1 += (double)g_phi1[i];
            v2 += (double)g_lse2[i];
            v3 += (double)g_phi2[i];
        }
        for (int i = tid; i < Nn; i += 256) cnt[i] = 0;
        __syncthreads();
        for (int i = tid; i < Nn; i += 256) atomicAdd(&cnt[g_idx[i]], 1);
        __syncthreads();
        double v4 = 0;
        for (int i = tid; i < Nn; i += 256) {
            int c = cnt[i];
            if (c > 0) { float em = (float)c / (float)Nn; v4 += (double)(em * logf(em + 1e-10f)); }
        }
        double vals[5] = {v0, v1, v2, v3, v4};
        int lane = tid & 31, warp = tid >> 5;
        #pragma unroll
        for (int v = 0; v < 5; ++v) {
            double x = vals[v];
            #pragma unroll
            for (int o = 16; o > 0; o >>= 1) x += __shfl_xor_sync(0xffffffffu, x, o);
            if (lane == 0) wred[warp*5 + v] = x;
        }
        __syncthreads();
        if (tid == 0) {
            double t[5] = {0, 0, 0, 0, 0};
            for (int w = 0; w < 8; ++w)
                for (int v = 0; v < 5; ++v) t[v] += wred[w*5 + v];
            double n = (double)Nn;
            double loss1 = (-0.1*t[0] + t[1]) / n;
            double loss2 = (-0.1*t[2]) / n + 0.1*log(n) + t[3]/n;
            out[2*OUTPLANE]     = (float)(0.25*(loss1 + loss2));
            out[2*OUTPLANE + 1] = (float)exp(-t[4]);
        }
        return;
    }
    int o = (blk - 1)*256 + tid;
    int w = o & 15, h = (o >> 4) & 15, c = (o >> 8) & 63, b = o >> 14;
    int i = (h*16 + w)*16 + b;
    out[o] = codebook[(g_idx[i] >> 3)*(2*Dd) + c];
    out[OUTPLANE + o] = z[o];
}

// ---------------- launch ----------------
extern "C" void kernel_launch(void* const* d_in, const int* in_sizes, int n_in,
                              void* d_out, int out_size) {
    const float* z        = (const float*)d_in[0];
    const float* codebook = (const float*)d_in[1];
    const float* w1       = (const float*)d_in[3];
    const float* b1       = (const float*)d_in[4];
    const float* w2       = (const float*)d_in[5];
    const float* b2       = (const float*)d_in[6];
    const float* noise    = (const float*)d_in[7];
    float* out = (float*)d_out;

    cudaFuncSetAttribute(k2, cudaFuncAttributeMaxDynamicSharedMemorySize, SMEM_BYTES);

    k0tr<<<257, 256>>>(z, w1, b1, w2, b2);
    k1<<<Nn/4, 128>>>(codebook, noise);
    {
        dim3 g(NRB, NCB);
        k2<<<g, 512, SMEM_BYTES>>>();
    }
    k3<<<32, 256>>>();
    k45<<<1025, 256>>>(z, codebook, out);
}